// round 10
// baseline (speedup 1.0000x reference)
#include <cuda_runtime.h>
#include <cuda_bf16.h>
#include <math.h>
#include <stdint.h>

// Problem constants
#define BATCH 2
#define SEQ 2048
#define DMODEL 1024
#define NHEADS 16
#define HDIM 64
#define TOPK 64
#define NROWS (BATCH * SEQ)          // 4096
#define BH (BATCH * NHEADS)          // 32
#define CAP 80                       // kept-slot capacity (64 + tie headroom)

// fused kernel tiling
#define QROWS 16
#define KCH 256
#define KSTR 65                      // K smem row stride (odd -> conflict-free)
#define SSTR 2048

// ---------------- scratch (device globals; allocation-free rule) -------------
__device__ float g_Q[(size_t)BH * SEQ * HDIM];   // [bh, s, d] 16MB
__device__ float g_K[(size_t)BH * SEQ * HDIM];   // 16MB
__device__ float g_V[(size_t)BH * SEQ * HDIM];   // 16MB
__device__ int   g_PI[(size_t)BH * SEQ * CAP];   // kept key indices
__device__ float g_PV[(size_t)BH * SEQ * CAP];   // kept normalized probs
__device__ int   g_CNT[(size_t)BH * SEQ];        // kept count per row
__device__ float g_O[(size_t)NROWS * DMODEL];    // attn output pre-Wo, 16MB

// ---------------- f32x2 packed-fma helpers ------------------------------------
typedef unsigned long long u64t;
__device__ __forceinline__ u64t dup2(float x) {
    u64t d;
    unsigned u = __float_as_uint(x);
    asm("mov.b64 %0, {%1, %1};" : "=l"(d) : "r"(u));
    return d;
}
__device__ __forceinline__ void ffma2(u64t& c, u64t a, u64t b) {
    asm("fma.rn.f32x2 %0, %1, %2, %0;" : "+l"(c) : "l"(a), "l"(b));
}
__device__ __forceinline__ void unpack2(u64t d, float& x, float& y) {
    unsigned lo, hi;
    asm("mov.b64 {%0, %1}, %2;" : "=r"(lo), "=r"(hi) : "l"(d));
    x = __uint_as_float(lo);
    y = __uint_as_float(hi);
}

// ---------------- tensor-core helpers ----------------------------------------
__device__ __forceinline__ uint32_t smem_u32(const void* p) {
    return (uint32_t)__cvta_generic_to_shared(p);
}
__device__ __forceinline__ void ldmA4(uint32_t addr, uint32_t& r0, uint32_t& r1,
                                      uint32_t& r2, uint32_t& r3) {
    asm volatile("ldmatrix.sync.aligned.m8n8.x4.shared.b16 {%0,%1,%2,%3}, [%4];"
                 : "=r"(r0), "=r"(r1), "=r"(r2), "=r"(r3) : "r"(addr));
}
__device__ __forceinline__ void ldmB2t(uint32_t addr, uint32_t& r0, uint32_t& r1) {
    asm volatile("ldmatrix.sync.aligned.m8n8.x2.trans.shared.b16 {%0,%1}, [%2];"
                 : "=r"(r0), "=r"(r1) : "r"(addr));
}
__device__ __forceinline__ void mma16816(float* c, uint32_t a0, uint32_t a1,
                                         uint32_t a2, uint32_t a3,
                                         uint32_t b0, uint32_t b1) {
    asm volatile(
        "mma.sync.aligned.m16n8k16.row.col.f32.bf16.bf16.f32 "
        "{%0,%1,%2,%3}, {%4,%5,%6,%7}, {%8,%9}, {%0,%1,%2,%3};"
        : "+f"(c[0]), "+f"(c[1]), "+f"(c[2]), "+f"(c[3])
        : "r"(a0), "r"(a1), "r"(a2), "r"(a3), "r"(b0), "r"(b1));
}
__device__ __forceinline__ void split_bf16(float x, __nv_bfloat16& hi, __nv_bfloat16& lo) {
    hi = __float2bfloat16(x);
    lo = __float2bfloat16(x - __bfloat162float(hi));
}

// ---------------- K1: 128x128x16 SGEMM w/ f32x2 (Q/K projections) ------------
__global__ __launch_bounds__(256) void gemm_kernel(
    const float* __restrict__ A,
    const float* __restrict__ W,
    const float* __restrict__ bias,
    int mode)   // 0 -> g_Q, 1 -> g_K
{
    __shared__ float As[16][132];
    __shared__ float Bs[16][128];

    const int K = DMODEL;
    const int NC = DMODEL;
    int tid = threadIdx.x;
    int tx = tid & 15;
    int ty = tid >> 4;
    int rowTile = blockIdx.y * 128;
    int colTile = blockIdx.x * 128;

    float* Op = (mode == 0) ? g_Q : g_K;

    int ar = tid >> 1;
    int ac8 = (tid & 1) * 8;
    int br = tid >> 4;
    int bc8 = (tid & 15) * 8;

    u64t acc2[4][8];
#pragma unroll
    for (int p = 0; p < 4; p++)
#pragma unroll
        for (int j = 0; j < 8; j++) acc2[p][j] = 0ull;

    const float* aptr = &A[(size_t)(rowTile + ar) * K];
    const float* bptr = &W[(size_t)colTile + bc8];

    {
        float4 a0 = *(const float4*)&aptr[ac8 + 0];
        float4 a1 = *(const float4*)&aptr[ac8 + 4];
        As[ac8 + 0][ar] = a0.x; As[ac8 + 1][ar] = a0.y;
        As[ac8 + 2][ar] = a0.z; As[ac8 + 3][ar] = a0.w;
        As[ac8 + 4][ar] = a1.x; As[ac8 + 5][ar] = a1.y;
        As[ac8 + 6][ar] = a1.z; As[ac8 + 7][ar] = a1.w;
        *(float4*)&Bs[br][bc8 + 0] = *(const float4*)&bptr[(size_t)br * NC + 0];
        *(float4*)&Bs[br][bc8 + 4] = *(const float4*)&bptr[(size_t)br * NC + 4];
    }
    __syncthreads();

    for (int k0 = 0; k0 < K; k0 += 16) {
        bool has = (k0 + 16) < K;
        float4 pa0, pa1, pb0, pb1;
        if (has) {
            pa0 = *(const float4*)&aptr[k0 + 16 + ac8 + 0];
            pa1 = *(const float4*)&aptr[k0 + 16 + ac8 + 4];
            pb0 = *(const float4*)&bptr[(size_t)(k0 + 16 + br) * NC + 0];
            pb1 = *(const float4*)&bptr[(size_t)(k0 + 16 + br) * NC + 4];
        }
#pragma unroll
        for (int kk = 0; kk < 16; kk++) {
            u64t a2[4];
#pragma unroll
            for (int p = 0; p < 4; p++)
                a2[p] = *(const u64t*)&As[kk][ty * 8 + 2 * p];
            float b[8];
            *(float4*)&b[0] = *(const float4*)&Bs[kk][tx * 8 + 0];
            *(float4*)&b[4] = *(const float4*)&Bs[kk][tx * 8 + 4];
            u64t bb[8];
#pragma unroll
            for (int j = 0; j < 8; j++) bb[j] = dup2(b[j]);
#pragma unroll
            for (int p = 0; p < 4; p++)
#pragma unroll
                for (int j = 0; j < 8; j++) ffma2(acc2[p][j], a2[p], bb[j]);
        }
        __syncthreads();
        if (has) {
            As[ac8 + 0][ar] = pa0.x; As[ac8 + 1][ar] = pa0.y;
            As[ac8 + 2][ar] = pa0.z; As[ac8 + 3][ar] = pa0.w;
            As[ac8 + 4][ar] = pa1.x; As[ac8 + 5][ar] = pa1.y;
            As[ac8 + 6][ar] = pa1.z; As[ac8 + 7][ar] = pa1.w;
            *(float4*)&Bs[br][bc8 + 0] = pb0;
            *(float4*)&Bs[br][bc8 + 4] = pb1;
            __syncthreads();
        }
    }

#pragma unroll
    for (int p = 0; p < 4; p++) {
        float r0[8], r1[8];
#pragma unroll
        for (int j = 0; j < 8; j++) unpack2(acc2[p][j], r0[j], r1[j]);
#pragma unroll
        for (int half = 0; half < 2; half++) {
            int m = rowTile + ty * 8 + 2 * p + half;
            int b = m / SEQ;
            int s = m - b * SEQ;
            const float* rr = half ? r1 : r0;
#pragma unroll
            for (int j = 0; j < 8; j++) {
                int n = colTile + tx * 8 + j;
                int h = n >> 6;
                int d = n & 63;
                Op[((size_t)(b * NHEADS + h) * SEQ + s) * HDIM + d] = rr[j] + bias[n];
            }
        }
    }
}

// ---------------- K1b: 128x128 split-bf16 tensor-core GEMM -------------------
__global__ __launch_bounds__(256) void gemm_bf16_kernel(
    const float* __restrict__ A,
    const float* __restrict__ W,
    const float* __restrict__ bias,
    float* __restrict__ outp,
    const float* __restrict__ gate,
    int mode)
{
    __shared__ __nv_bfloat16 Ahi[128][40], Alo[128][40];
    __shared__ __nv_bfloat16 Bhi[32][136], Blo[32][136];

    const int K = DMODEL;
    const int NC = DMODEL;
    int tid = threadIdx.x;
    int lane = tid & 31;
    int wid = tid >> 5;
    int wm = wid & 1;
    int wn = wid >> 1;
    int rowTile = blockIdx.y * 128;
    int colTile = blockIdx.x * 128;

    const float* Ap = (mode == 3) ? g_O : A;

    int ar = tid >> 1, ac = (tid & 1) * 16;
    int br = tid >> 3, bc = (tid & 7) * 16;
    const float* aptr = &Ap[(size_t)(rowTile + ar) * K + ac];
    const float* bptr = &W[(size_t)br * NC + colTile + bc];

    float acc[4][4][4];
#pragma unroll
    for (int mi = 0; mi < 4; mi++)
#pragma unroll
        for (int ni = 0; ni < 4; ni++)
#pragma unroll
            for (int r = 0; r < 4; r++) acc[mi][ni][r] = 0.0f;

    float4 pa[4], pb[4];
#pragma unroll
    for (int t = 0; t < 4; t++) {
        pa[t] = *(const float4*)&aptr[t * 4];
        pb[t] = *(const float4*)&bptr[t * 4];
    }
#pragma unroll
    for (int t = 0; t < 4; t++) {
        float v[4] = {pa[t].x, pa[t].y, pa[t].z, pa[t].w};
        __nv_bfloat16 h0, l0, h1, l1;
        split_bf16(v[0], h0, l0); split_bf16(v[1], h1, l1);
        *(__nv_bfloat162*)&Ahi[ar][ac + t * 4] = __nv_bfloat162(h0, h1);
        *(__nv_bfloat162*)&Alo[ar][ac + t * 4] = __nv_bfloat162(l0, l1);
        split_bf16(v[2], h0, l0); split_bf16(v[3], h1, l1);
        *(__nv_bfloat162*)&Ahi[ar][ac + t * 4 + 2] = __nv_bfloat162(h0, h1);
        *(__nv_bfloat162*)&Alo[ar][ac + t * 4 + 2] = __nv_bfloat162(l0, l1);
        float w[4] = {pb[t].x, pb[t].y, pb[t].z, pb[t].w};
        split_bf16(w[0], h0, l0); split_bf16(w[1], h1, l1);
        *(__nv_bfloat162*)&Bhi[br][bc + t * 4] = __nv_bfloat162(h0, h1);
        *(__nv_bfloat162*)&Blo[br][bc + t * 4] = __nv_bfloat162(l0, l1);
        split_bf16(w[2], h0, l0); split_bf16(w[3], h1, l1);
        *(__nv_bfloat162*)&Bhi[br][bc + t * 4 + 2] = __nv_bfloat162(h0, h1);
        *(__nv_bfloat162*)&Blo[br][bc + t * 4 + 2] = __nv_bfloat162(l0, l1);
    }
    __syncthreads();

    for (int s = 0; s < K / 32; s++) {
        bool has = (s + 1) < K / 32;
        if (has) {
            int k0 = (s + 1) * 32;
#pragma unroll
            for (int t = 0; t < 4; t++) {
                pa[t] = *(const float4*)&aptr[k0 + t * 4];
                pb[t] = *(const float4*)&bptr[(size_t)k0 * NC + t * 4];
            }
        }
#pragma unroll
        for (int ks = 0; ks < 2; ks++) {
            int kk = ks * 16;
            uint32_t bhr[4][2], blr[4][2];
#pragma unroll
            for (int ni = 0; ni < 4; ni++) {
                ldmB2t(smem_u32(&Bhi[kk + (lane & 15)][wn * 32 + ni * 8]), bhr[ni][0], bhr[ni][1]);
                ldmB2t(smem_u32(&Blo[kk + (lane & 15)][wn * 32 + ni * 8]), blr[ni][0], blr[ni][1]);
            }
#pragma unroll
            for (int mi = 0; mi < 4; mi++) {
                int arow = wm * 64 + mi * 16 + (lane & 15);
                int acol = kk + ((lane >> 4) << 3);
                uint32_t ah0, ah1, ah2, ah3, al0, al1, al2, al3;
                ldmA4(smem_u32(&Ahi[arow][acol]), ah0, ah1, ah2, ah3);
                ldmA4(smem_u32(&Alo[arow][acol]), al0, al1, al2, al3);
#pragma unroll
                for (int ni = 0; ni < 4; ni++) {
                    mma16816(acc[mi][ni], ah0, ah1, ah2, ah3, bhr[ni][0], bhr[ni][1]);
                    mma16816(acc[mi][ni], al0, al1, al2, al3, bhr[ni][0], bhr[ni][1]);
                    mma16816(acc[mi][ni], ah0, ah1, ah2, ah3, blr[ni][0], blr[ni][1]);
                }
            }
        }
        __syncthreads();
        if (has) {
#pragma unroll
            for (int t = 0; t < 4; t++) {
                float v[4] = {pa[t].x, pa[t].y, pa[t].z, pa[t].w};
                __nv_bfloat16 h0, l0, h1, l1;
                split_bf16(v[0], h0, l0); split_bf16(v[1], h1, l1);
                *(__nv_bfloat162*)&Ahi[ar][ac + t * 4] = __nv_bfloat162(h0, h1);
                *(__nv_bfloat162*)&Alo[ar][ac + t * 4] = __nv_bfloat162(l0, l1);
                split_bf16(v[2], h0, l0); split_bf16(v[3], h1, l1);
                *(__nv_bfloat162*)&Ahi[ar][ac + t * 4 + 2] = __nv_bfloat162(h0, h1);
                *(__nv_bfloat162*)&Alo[ar][ac + t * 4 + 2] = __nv_bfloat162(l0, l1);
                float w[4] = {pb[t].x, pb[t].y, pb[t].z, pb[t].w};
                split_bf16(w[0], h0, l0); split_bf16(w[1], h1, l1);
                *(__nv_bfloat162*)&Bhi[br][bc + t * 4] = __nv_bfloat162(h0, h1);
                *(__nv_bfloat162*)&Blo[br][bc + t * 4] = __nv_bfloat162(l0, l1);
                split_bf16(w[2], h0, l0); split_bf16(w[3], h1, l1);
                *(__nv_bfloat162*)&Bhi[br][bc + t * 4 + 2] = __nv_bfloat162(h0, h1);
                *(__nv_bfloat162*)&Blo[br][bc + t * 4 + 2] = __nv_bfloat162(l0, l1);
            }
            __syncthreads();
        }
    }

#pragma unroll
    for (int mi = 0; mi < 4; mi++) {
#pragma unroll
        for (int ni = 0; ni < 4; ni++) {
            int row0 = rowTile + wm * 64 + mi * 16 + (lane >> 2);
            int col0 = colTile + wn * 32 + ni * 8 + (lane & 3) * 2;
            float b0 = bias[col0], b1 = bias[col0 + 1];
#pragma unroll
            for (int half = 0; half < 2; half++) {
                int m = row0 + half * 8;
                float v0 = acc[mi][ni][half * 2 + 0] + b0;
                float v1 = acc[mi][ni][half * 2 + 1] + b1;
                if (mode == 2) {
                    int b = m / SEQ;
                    int ss = m - b * SEQ;
                    int h = col0 >> 6;
                    int d = col0 & 63;
                    float2* dst = (float2*)&g_V[((size_t)(b * NHEADS + h) * SEQ + ss) * HDIM + d];
                    *dst = make_float2(v0, v1);
                } else {
                    float gm = gate[m];
                    float2* dst = (float2*)&outp[(size_t)m * DMODEL + col0];
                    *dst = make_float2(v0 * gm, v1 * gm);
                }
            }
        }
    }
}

// ---------------- fused: scores + exact top-64 + softmax -> sparse -----------
// One CTA = 16 query rows of one (b,h). Scores stay in smem; g_P eliminated.
__device__ __forceinline__ int warp_digit_select(const unsigned* histw, int lane, int& kk)
{
    unsigned c[8];
#pragma unroll
    for (int j = 0; j < 8; j++) c[j] = histw[lane * 8 + j];
    unsigned sum8 = 0;
#pragma unroll
    for (int j = 0; j < 8; j++) sum8 += c[j];
    unsigned s = sum8;
#pragma unroll
    for (int off = 1; off < 32; off <<= 1) {
        unsigned t = __shfl_down_sync(0xFFFFFFFFu, s, off);
        if (lane + off < 32) s += t;
    }
    unsigned sufExcl = s - sum8;   // sum over lanes > lane
    bool has = (sufExcl < (unsigned)kk) && (s >= (unsigned)kk);
    int sel = 0;
    int newkk = kk;
    if (has) {
        unsigned run = sufExcl;
#pragma unroll
        for (int j = 7; j >= 0; j--) {
            run += c[j];
            if (run >= (unsigned)kk) { sel = lane * 8 + j; newkk = kk - (int)(run - c[j]); break; }
        }
    }
    unsigned bal = __ballot_sync(0xFFFFFFFFu, has);
    int src = __ffs(bal) - 1;
    sel = __shfl_sync(0xFFFFFFFFu, sel, src);
    kk = __shfl_sync(0xFFFFFFFFu, newkk, src);
    return sel;
}

extern __shared__ char fsmem[];

__global__ __launch_bounds__(512) void fused_attn_kernel()
{
    // smem layout (bytes):
    float* S  = (float*)fsmem;                          //  16*2048*4 = 131072
    float* Kl = (float*)(fsmem + 131072);               // 256*65*4   =  66560
    float* Qp = (float*)(fsmem + 131072 + 66560);       //   8*64*2*4 =   4096
    unsigned* hist = (unsigned*)(fsmem + 201728);       //  16*256*4  =  16384
    int*   pib = (int*)(fsmem + 218112);                //  16*80*4   =   5120
    float* pvb = (float*)(fsmem + 223232);              //  16*80*4   =   5120
                                                        // total 228352

    int qb = (int)gridDim.x - 1 - (int)blockIdx.x;      // heavy blocks first
    int bh = blockIdx.y;
    int q0 = qb * QROWS;
    int tid = threadIdx.x;
    int lane = tid & 31;
    int w = tid >> 5;                                   // 0..15

    const float* Qg = &g_Q[((size_t)bh * SEQ + q0) * HDIM];
    const float* Kgb = &g_K[(size_t)bh * SEQ * HDIM];

    // ---- load + scale Q tile: Qp[pair][d] = (Q[2p][d], Q[2p+1][d]) * 0.125 ----
    if (tid < 256) {
        int r = tid >> 4;
        int d4 = (tid & 15) << 2;
        float4 qv = *(const float4*)&Qg[(size_t)r * HDIM + d4];
        float vals[4] = {qv.x, qv.y, qv.z, qv.w};
        int p = r >> 1, half = r & 1;
#pragma unroll
        for (int j = 0; j < 4; j++)
            Qp[(p * 64 + d4 + j) * 2 + half] = vals[j] * 0.125f;
    }

    int Lmax = q0 + QROWS;
    int nch = (Lmax + KCH - 1) / KCH;

    int rg = w >> 2;            // 0..3 -> rows 4rg..4rg+3
    int ks = w & 3;             // 0..3 -> 64-k slice within 256 chunk
    int k0l = ks * 64 + lane;   // this lane's k (and k0l+32)

    const u64t* qpa = (const u64t*)&Qp[(2 * rg) * 128];
    const u64t* qpb = (const u64t*)&Qp[(2 * rg + 1) * 128];

    for (int ch = 0; ch < nch; ch++) {
        __syncthreads();
        // load K chunk [256 x 64] -> Kl[k][d] (stride 65)
        {
            int kbase = ch * KCH;
#pragma unroll
            for (int t = 0; t < 8; t++) {
                int idx = tid + t * 512;
                int k = idx >> 4;
                int d4 = (idx & 15) << 2;
                float4 kv = *(const float4*)&Kgb[(size_t)(kbase + k) * HDIM + d4];
                Kl[k * KSTR + d4 + 0] = kv.x;
                Kl[k * KSTR + d4 + 1] = kv.y;
                Kl[k * KSTR + d4 + 2] = kv.z;
                Kl[k * KSTR + d4 + 3] = kv.w;
            }
        }
        __syncthreads();

        u64t acc00 = 0ull, acc01 = 0ull, acc10 = 0ull, acc11 = 0ull;
        const float* kr0 = &Kl[k0l * KSTR];
        const float* kr1 = &Kl[(k0l + 32) * KSTR];
#pragma unroll 16
        for (int d = 0; d < 64; d++) {
            u64t qa = qpa[d];
            u64t qb2 = qpb[d];
            u64t b0 = dup2(kr0[d]);
            u64t b1 = dup2(kr1[d]);
            ffma2(acc00, qa, b0);
            ffma2(acc01, qa, b1);
            ffma2(acc10, qb2, b0);
            ffma2(acc11, qb2, b1);
        }
        int kc = ch * KCH + k0l;
        float x0, x1;
        unpack2(acc00, x0, x1);
        S[(4 * rg + 0) * SSTR + kc] = x0;
        S[(4 * rg + 1) * SSTR + kc] = x1;
        unpack2(acc01, x0, x1);
        S[(4 * rg + 0) * SSTR + kc + 32] = x0;
        S[(4 * rg + 1) * SSTR + kc + 32] = x1;
        unpack2(acc10, x0, x1);
        S[(4 * rg + 2) * SSTR + kc] = x0;
        S[(4 * rg + 3) * SSTR + kc] = x1;
        unpack2(acc11, x0, x1);
        S[(4 * rg + 2) * SSTR + kc + 32] = x0;
        S[(4 * rg + 3) * SSTR + kc + 32] = x1;
    }
    __syncthreads();

    // ---- selection phase: warp w handles row w ----
    {
        int r = w;
        int q = q0 + r;
        int L = q + 1;
        const float* Srow = &S[r * SSTR];
        unsigned* histw = &hist[w * 256];
        int* pibw = &pib[w * CAP];
        float* pvbw = &pvb[w * CAP];

        bool doSel = (L > TOPK);
        int niter = (L + 31) >> 5;

#pragma unroll
        for (int j = 0; j < 8; j++) histw[lane * 8 + j] = 0;
        __syncwarp();

        // pass over row: max + top-byte histogram (match_any aggregated, no atomics)
        float m = -INFINITY;
        for (int it = 0; it < niter; it++) {
            int i = lane + (it << 5);
            bool valid = i < L;
            float v = valid ? Srow[i] : 0.0f;
            if (valid) m = fmaxf(m, v);
            if (doSel) {
                unsigned u = __float_as_uint(v);
                unsigned key = (u & 0x80000000u) ? ~u : (u | 0x80000000u);
                int bin = valid ? (int)(key >> 24) : 256;
                unsigned grp = __match_any_sync(0xFFFFFFFFu, bin);
                if (valid && lane == (__ffs(grp) - 1))
                    histw[bin] += __popc(grp);
            }
        }
#pragma unroll
        for (int off = 16; off; off >>= 1)
            m = fmaxf(m, __shfl_xor_sync(0xFFFFFFFFu, m, off));

        float thresh = -INFINITY;
        if (doSel) {
            __syncwarp();
            int kk = TOPK;
            int sel = warp_digit_select(histw, lane, kk);
            unsigned prefix = (unsigned)sel << 24;
            unsigned himask = 0xFF000000u;
            for (int p = 16; p >= 0; p -= 8) {
#pragma unroll
                for (int j = 0; j < 8; j++) histw[lane * 8 + j] = 0;
                __syncwarp();
                for (int it = 0; it < niter; it++) {
                    int i = lane + (it << 5);
                    bool valid = i < L;
                    unsigned key = 0;
                    if (valid) {
                        unsigned u = __float_as_uint(Srow[i]);
                        key = (u & 0x80000000u) ? ~u : (u | 0x80000000u);
                    }
                    bool ok = valid && ((key & himask) == prefix);
                    int bin = ok ? (int)((key >> p) & 255u) : 256;
                    unsigned grp = __match_any_sync(0xFFFFFFFFu, bin);
                    if (ok && lane == (__ffs(grp) - 1))
                        histw[bin] += __popc(grp);
                }
                __syncwarp();
                sel = warp_digit_select(histw, lane, kk);
                prefix |= (unsigned)sel << p;
                himask |= 0xFFu << p;
            }
            unsigned u = (prefix & 0x80000000u) ? (prefix & 0x7FFFFFFFu) : ~prefix;
            thresh = __uint_as_float(u);
        }

        // compact kept entries (ballot-ordered, deterministic) + exp
        int base = 0;
        for (int it = 0; it < niter; it++) {
            int i = lane + (it << 5);
            bool valid = i < L;
            float v = valid ? Srow[i] : 0.0f;
            bool keep = valid && (v >= thresh);
            unsigned bal = __ballot_sync(0xFFFFFFFFu, keep);
            int pos = base + __popc(bal & ((1u << lane) - 1u));
            if (keep && pos < CAP) {
                pibw[pos] = i;
                pvbw[pos] = __expf(v - m);
            }
            base += __popc(bal);
        }
        int cnt = min(base, CAP);
        __syncwarp();
        float ss = 0.0f;
        for (int j = lane; j < cnt; j += 32) ss += pvbw[j];
#pragma unroll
        for (int off = 16; off; off >>= 1)
            ss += __shfl_xor_sync(0xFFFFFFFFu, ss, off);
        float inv = 1.0f / ss;

        int grow = bh * SEQ + q;
        for (int j = lane; j < cnt; j += 32) {
            g_PI[(size_t)grow * CAP + j] = pibw[j];
            g_PV[(size_t)grow * CAP + j] = pvbw[j] * inv;
        }
        if (lane == 0) g_CNT[grow] = cnt;
    }
}

// ---------------- K4: sparse O = P @ V (one warp per query row, fp32) --------
__global__ __launch_bounds__(256) void av_sparse_kernel()
{
    int row = blockIdx.x * 8 + (threadIdx.x >> 5);
    int lane = threadIdx.x & 31;
    int bh = row >> 11;
    int s = row & (SEQ - 1);
    int b = bh >> 4;
    int h = bh & 15;

    int cnt = g_CNT[row];
    const float* Vb = &g_V[(size_t)bh * SEQ * HDIM];
    const int* PI = &g_PI[(size_t)row * CAP];
    const float* PV = &g_PV[(size_t)row * CAP];

    float a0 = 0.0f, a1 = 0.0f;
    for (int c = 0; c < cnt; c += 32) {
        int myIdx = 0;
        float myP = 0.0f;
        if (c + lane < cnt) {
            myIdx = PI[c + lane];
            myP = PV[c + lane];
        }
        int nn = min(32, cnt - c);
#pragma unroll 8
        for (int jj = 0; jj < nn; jj++) {
            int idx = __shfl_sync(0xFFFFFFFFu, myIdx, jj);
            float p = __shfl_sync(0xFFFFFFFFu, myP, jj);
            float2 v = *(const float2*)&Vb[(size_t)idx * HDIM + lane * 2];
            a0 = fmaf(p, v.x, a0);
            a1 = fmaf(p, v.y, a1);
        }
    }

    float2* dst = (float2*)&g_O[(size_t)(b * SEQ + s) * DMODEL + h * HDIM + lane * 2];
    *dst = make_float2(a0, a1);
}

// ---------------- launch ------------------------------------------------------
#define FUSED_SMEM 228352

extern "C" void kernel_launch(void* const* d_in, const int* in_sizes, int n_in,
                              void* d_out, int out_size)
{
    const float* h_ssm = (const float*)d_in[0];
    const float* gate  = (const float*)d_in[1];
    const float* Wq = (const float*)d_in[2];
    const float* bq = (const float*)d_in[3];
    const float* Wk = (const float*)d_in[4];
    const float* bk = (const float*)d_in[5];
    const float* Wv = (const float*)d_in[6];
    const float* bv = (const float*)d_in[7];
    const float* Wo = (const float*)d_in[8];
    const float* bo = (const float*)d_in[9];
    float* out = (float*)d_out;

    cudaFuncSetAttribute(fused_attn_kernel,
                         cudaFuncAttributeMaxDynamicSharedMemorySize, FUSED_SMEM);

    dim3 gProj(DMODEL / 128, NROWS / 128);          // (8, 32)
    gemm_kernel<<<gProj, 256>>>(h_ssm, Wq, bq, 0);
    gemm_kernel<<<gProj, 256>>>(h_ssm, Wk, bk, 1);
    gemm_bf16_kernel<<<gProj, 256>>>(h_ssm, Wv, bv, nullptr, nullptr, 2);

    fused_attn_kernel<<<dim3(SEQ / QROWS, BH), 512, FUSED_SMEM>>>();
    av_sparse_kernel<<<dim3(BH * SEQ / 8), 256>>>();

    gemm_bf16_kernel<<<gProj, 256>>>(nullptr, Wo, bo, out, gate, 3);
}

// round 14
// speedup vs baseline: 1.1348x; 1.1348x over previous
#include <cuda_runtime.h>
#include <cuda_bf16.h>
#include <math.h>
#include <stdint.h>

// Problem constants
#define BATCH 2
#define SEQ 2048
#define DMODEL 1024
#define NHEADS 16
#define HDIM 64
#define TOPK 64
#define NROWS (BATCH * SEQ)          // 4096
#define BH (BATCH * NHEADS)          // 32
#define CAP 80                       // kept-slot capacity (64 + tie headroom)

// ---------------- scratch (device globals; allocation-free rule) -------------
__device__ float g_Q[(size_t)BH * SEQ * HDIM];   // [bh, s, d] 16MB
__device__ float g_K[(size_t)BH * SEQ * HDIM];   // 16MB
__device__ float g_V[(size_t)BH * SEQ * HDIM];   // 16MB
__device__ float g_P[(size_t)BH * SEQ * SEQ];    // raw scores, 512MB
__device__ int   g_PI[(size_t)BH * SEQ * CAP];   // kept key indices
__device__ float g_PV[(size_t)BH * SEQ * CAP];   // kept normalized probs
__device__ int   g_CNT[(size_t)BH * SEQ];        // kept count per row
__device__ float g_O[(size_t)NROWS * DMODEL];    // attn output pre-Wo, 16MB

// ---------------- f32x2 packed-fma helpers ------------------------------------
typedef unsigned long long u64t;
__device__ __forceinline__ u64t dup2(float x) {
    u64t d;
    unsigned u = __float_as_uint(x);
    asm("mov.b64 %0, {%1, %1};" : "=l"(d) : "r"(u));
    return d;
}
__device__ __forceinline__ void ffma2(u64t& c, u64t a, u64t b) {
    asm("fma.rn.f32x2 %0, %1, %2, %0;" : "+l"(c) : "l"(a), "l"(b));
}
__device__ __forceinline__ void unpack2(u64t d, float& x, float& y) {
    unsigned lo, hi;
    asm("mov.b64 {%0, %1}, %2;" : "=r"(lo), "=r"(hi) : "l"(d));
    x = __uint_as_float(lo);
    y = __uint_as_float(hi);
}

// ---------------- tensor-core helpers ----------------------------------------
__device__ __forceinline__ uint32_t smem_u32(const void* p) {
    return (uint32_t)__cvta_generic_to_shared(p);
}
__device__ __forceinline__ void ldmA4(uint32_t addr, uint32_t& r0, uint32_t& r1,
                                      uint32_t& r2, uint32_t& r3) {
    asm volatile("ldmatrix.sync.aligned.m8n8.x4.shared.b16 {%0,%1,%2,%3}, [%4];"
                 : "=r"(r0), "=r"(r1), "=r"(r2), "=r"(r3) : "r"(addr));
}
__device__ __forceinline__ void ldmB2t(uint32_t addr, uint32_t& r0, uint32_t& r1) {
    asm volatile("ldmatrix.sync.aligned.m8n8.x2.trans.shared.b16 {%0,%1}, [%2];"
                 : "=r"(r0), "=r"(r1) : "r"(addr));
}
__device__ __forceinline__ void mma16816(float* c, uint32_t a0, uint32_t a1,
                                         uint32_t a2, uint32_t a3,
                                         uint32_t b0, uint32_t b1) {
    asm volatile(
        "mma.sync.aligned.m16n8k16.row.col.f32.bf16.bf16.f32 "
        "{%0,%1,%2,%3}, {%4,%5,%6,%7}, {%8,%9}, {%0,%1,%2,%3};"
        : "+f"(c[0]), "+f"(c[1]), "+f"(c[2]), "+f"(c[3])
        : "r"(a0), "r"(a1), "r"(a2), "r"(a3), "r"(b0), "r"(b1));
}
__device__ __forceinline__ void split_bf16(float x, __nv_bfloat16& hi, __nv_bfloat16& lo) {
    hi = __float2bfloat16(x);
    lo = __float2bfloat16(x - __bfloat162float(hi));
}

// ---------------- K1: 128x128x16 SGEMM w/ f32x2 (Q/K projections) ------------
__global__ __launch_bounds__(256) void gemm_kernel(
    const float* __restrict__ A,
    const float* __restrict__ W,
    const float* __restrict__ bias,
    int mode)   // 0 -> g_Q, 1 -> g_K
{
    __shared__ float As[16][132];
    __shared__ float Bs[16][128];

    const int K = DMODEL;
    const int NC = DMODEL;
    int tid = threadIdx.x;
    int tx = tid & 15;
    int ty = tid >> 4;
    int rowTile = blockIdx.y * 128;
    int colTile = blockIdx.x * 128;

    float* Op = (mode == 0) ? g_Q : g_K;

    int ar = tid >> 1;
    int ac8 = (tid & 1) * 8;
    int br = tid >> 4;
    int bc8 = (tid & 15) * 8;

    u64t acc2[4][8];
#pragma unroll
    for (int p = 0; p < 4; p++)
#pragma unroll
        for (int j = 0; j < 8; j++) acc2[p][j] = 0ull;

    const float* aptr = &A[(size_t)(rowTile + ar) * K];
    const float* bptr = &W[(size_t)colTile + bc8];

    {
        float4 a0 = *(const float4*)&aptr[ac8 + 0];
        float4 a1 = *(const float4*)&aptr[ac8 + 4];
        As[ac8 + 0][ar] = a0.x; As[ac8 + 1][ar] = a0.y;
        As[ac8 + 2][ar] = a0.z; As[ac8 + 3][ar] = a0.w;
        As[ac8 + 4][ar] = a1.x; As[ac8 + 5][ar] = a1.y;
        As[ac8 + 6][ar] = a1.z; As[ac8 + 7][ar] = a1.w;
        *(float4*)&Bs[br][bc8 + 0] = *(const float4*)&bptr[(size_t)br * NC + 0];
        *(float4*)&Bs[br][bc8 + 4] = *(const float4*)&bptr[(size_t)br * NC + 4];
    }
    __syncthreads();

    for (int k0 = 0; k0 < K; k0 += 16) {
        bool has = (k0 + 16) < K;
        float4 pa0, pa1, pb0, pb1;
        if (has) {
            pa0 = *(const float4*)&aptr[k0 + 16 + ac8 + 0];
            pa1 = *(const float4*)&aptr[k0 + 16 + ac8 + 4];
            pb0 = *(const float4*)&bptr[(size_t)(k0 + 16 + br) * NC + 0];
            pb1 = *(const float4*)&bptr[(size_t)(k0 + 16 + br) * NC + 4];
        }
#pragma unroll
        for (int kk = 0; kk < 16; kk++) {
            u64t a2[4];
#pragma unroll
            for (int p = 0; p < 4; p++)
                a2[p] = *(const u64t*)&As[kk][ty * 8 + 2 * p];
            float b[8];
            *(float4*)&b[0] = *(const float4*)&Bs[kk][tx * 8 + 0];
            *(float4*)&b[4] = *(const float4*)&Bs[kk][tx * 8 + 4];
            u64t bb[8];
#pragma unroll
            for (int j = 0; j < 8; j++) bb[j] = dup2(b[j]);
#pragma unroll
            for (int p = 0; p < 4; p++)
#pragma unroll
                for (int j = 0; j < 8; j++) ffma2(acc2[p][j], a2[p], bb[j]);
        }
        __syncthreads();
        if (has) {
            As[ac8 + 0][ar] = pa0.x; As[ac8 + 1][ar] = pa0.y;
            As[ac8 + 2][ar] = pa0.z; As[ac8 + 3][ar] = pa0.w;
            As[ac8 + 4][ar] = pa1.x; As[ac8 + 5][ar] = pa1.y;
            As[ac8 + 6][ar] = pa1.z; As[ac8 + 7][ar] = pa1.w;
            *(float4*)&Bs[br][bc8 + 0] = pb0;
            *(float4*)&Bs[br][bc8 + 4] = pb1;
            __syncthreads();
        }
    }

#pragma unroll
    for (int p = 0; p < 4; p++) {
        float r0[8], r1[8];
#pragma unroll
        for (int j = 0; j < 8; j++) unpack2(acc2[p][j], r0[j], r1[j]);
#pragma unroll
        for (int half = 0; half < 2; half++) {
            int m = rowTile + ty * 8 + 2 * p + half;
            int b = m / SEQ;
            int s = m - b * SEQ;
            const float* rr = half ? r1 : r0;
#pragma unroll
            for (int j = 0; j < 8; j++) {
                int n = colTile + tx * 8 + j;
                int h = n >> 6;
                int d = n & 63;
                Op[((size_t)(b * NHEADS + h) * SEQ + s) * HDIM + d] = rr[j] + bias[n];
            }
        }
    }
}

// ---------------- K1b: 128x128 split-bf16 tensor-core GEMM -------------------
__global__ __launch_bounds__(256) void gemm_bf16_kernel(
    const float* __restrict__ A,
    const float* __restrict__ W,
    const float* __restrict__ bias,
    float* __restrict__ outp,
    const float* __restrict__ gate,
    int mode)
{
    __shared__ __nv_bfloat16 Ahi[128][40], Alo[128][40];
    __shared__ __nv_bfloat16 Bhi[32][136], Blo[32][136];

    const int K = DMODEL;
    const int NC = DMODEL;
    int tid = threadIdx.x;
    int lane = tid & 31;
    int wid = tid >> 5;
    int wm = wid & 1;
    int wn = wid >> 1;
    int rowTile = blockIdx.y * 128;
    int colTile = blockIdx.x * 128;

    const float* Ap = (mode == 3) ? g_O : A;

    int ar = tid >> 1, ac = (tid & 1) * 16;
    int br = tid >> 3, bc = (tid & 7) * 16;
    const float* aptr = &Ap[(size_t)(rowTile + ar) * K + ac];
    const float* bptr = &W[(size_t)br * NC + colTile + bc];

    float acc[4][4][4];
#pragma unroll
    for (int mi = 0; mi < 4; mi++)
#pragma unroll
        for (int ni = 0; ni < 4; ni++)
#pragma unroll
            for (int r = 0; r < 4; r++) acc[mi][ni][r] = 0.0f;

    float4 pa[4], pb[4];
#pragma unroll
    for (int t = 0; t < 4; t++) {
        pa[t] = *(const float4*)&aptr[t * 4];
        pb[t] = *(const float4*)&bptr[t * 4];
    }
#pragma unroll
    for (int t = 0; t < 4; t++) {
        float v[4] = {pa[t].x, pa[t].y, pa[t].z, pa[t].w};
        __nv_bfloat16 h0, l0, h1, l1;
        split_bf16(v[0], h0, l0); split_bf16(v[1], h1, l1);
        *(__nv_bfloat162*)&Ahi[ar][ac + t * 4] = __nv_bfloat162(h0, h1);
        *(__nv_bfloat162*)&Alo[ar][ac + t * 4] = __nv_bfloat162(l0, l1);
        split_bf16(v[2], h0, l0); split_bf16(v[3], h1, l1);
        *(__nv_bfloat162*)&Ahi[ar][ac + t * 4 + 2] = __nv_bfloat162(h0, h1);
        *(__nv_bfloat162*)&Alo[ar][ac + t * 4 + 2] = __nv_bfloat162(l0, l1);
        float w[4] = {pb[t].x, pb[t].y, pb[t].z, pb[t].w};
        split_bf16(w[0], h0, l0); split_bf16(w[1], h1, l1);
        *(__nv_bfloat162*)&Bhi[br][bc + t * 4] = __nv_bfloat162(h0, h1);
        *(__nv_bfloat162*)&Blo[br][bc + t * 4] = __nv_bfloat162(l0, l1);
        split_bf16(w[2], h0, l0); split_bf16(w[3], h1, l1);
        *(__nv_bfloat162*)&Bhi[br][bc + t * 4 + 2] = __nv_bfloat162(h0, h1);
        *(__nv_bfloat162*)&Blo[br][bc + t * 4 + 2] = __nv_bfloat162(l0, l1);
    }
    __syncthreads();

    for (int s = 0; s < K / 32; s++) {
        bool has = (s + 1) < K / 32;
        if (has) {
            int k0 = (s + 1) * 32;
#pragma unroll
            for (int t = 0; t < 4; t++) {
                pa[t] = *(const float4*)&aptr[k0 + t * 4];
                pb[t] = *(const float4*)&bptr[(size_t)k0 * NC + t * 4];
            }
        }
#pragma unroll
        for (int ks = 0; ks < 2; ks++) {
            int kk = ks * 16;
            uint32_t bhr[4][2], blr[4][2];
#pragma unroll
            for (int ni = 0; ni < 4; ni++) {
                ldmB2t(smem_u32(&Bhi[kk + (lane & 15)][wn * 32 + ni * 8]), bhr[ni][0], bhr[ni][1]);
                ldmB2t(smem_u32(&Blo[kk + (lane & 15)][wn * 32 + ni * 8]), blr[ni][0], blr[ni][1]);
            }
#pragma unroll
            for (int mi = 0; mi < 4; mi++) {
                int arow = wm * 64 + mi * 16 + (lane & 15);
                int acol = kk + ((lane >> 4) << 3);
                uint32_t ah0, ah1, ah2, ah3, al0, al1, al2, al3;
                ldmA4(smem_u32(&Ahi[arow][acol]), ah0, ah1, ah2, ah3);
                ldmA4(smem_u32(&Alo[arow][acol]), al0, al1, al2, al3);
#pragma unroll
                for (int ni = 0; ni < 4; ni++) {
                    mma16816(acc[mi][ni], ah0, ah1, ah2, ah3, bhr[ni][0], bhr[ni][1]);
                    mma16816(acc[mi][ni], al0, al1, al2, al3, bhr[ni][0], bhr[ni][1]);
                    mma16816(acc[mi][ni], ah0, ah1, ah2, ah3, blr[ni][0], blr[ni][1]);
                }
            }
        }
        __syncthreads();
        if (has) {
#pragma unroll
            for (int t = 0; t < 4; t++) {
                float v[4] = {pa[t].x, pa[t].y, pa[t].z, pa[t].w};
                __nv_bfloat16 h0, l0, h1, l1;
                split_bf16(v[0], h0, l0); split_bf16(v[1], h1, l1);
                *(__nv_bfloat162*)&Ahi[ar][ac + t * 4] = __nv_bfloat162(h0, h1);
                *(__nv_bfloat162*)&Alo[ar][ac + t * 4] = __nv_bfloat162(l0, l1);
                split_bf16(v[2], h0, l0); split_bf16(v[3], h1, l1);
                *(__nv_bfloat162*)&Ahi[ar][ac + t * 4 + 2] = __nv_bfloat162(h0, h1);
                *(__nv_bfloat162*)&Alo[ar][ac + t * 4 + 2] = __nv_bfloat162(l0, l1);
                float w[4] = {pb[t].x, pb[t].y, pb[t].z, pb[t].w};
                split_bf16(w[0], h0, l0); split_bf16(w[1], h1, l1);
                *(__nv_bfloat162*)&Bhi[br][bc + t * 4] = __nv_bfloat162(h0, h1);
                *(__nv_bfloat162*)&Blo[br][bc + t * 4] = __nv_bfloat162(l0, l1);
                split_bf16(w[2], h0, l0); split_bf16(w[3], h1, l1);
                *(__nv_bfloat162*)&Bhi[br][bc + t * 4 + 2] = __nv_bfloat162(h0, h1);
                *(__nv_bfloat162*)&Blo[br][bc + t * 4 + 2] = __nv_bfloat162(l0, l1);
            }
            __syncthreads();
        }
    }

#pragma unroll
    for (int mi = 0; mi < 4; mi++) {
#pragma unroll
        for (int ni = 0; ni < 4; ni++) {
            int row0 = rowTile + wm * 64 + mi * 16 + (lane >> 2);
            int col0 = colTile + wn * 32 + ni * 8 + (lane & 3) * 2;
            float b0 = bias[col0], b1 = bias[col0 + 1];
#pragma unroll
            for (int half = 0; half < 2; half++) {
                int m = row0 + half * 8;
                float v0 = acc[mi][ni][half * 2 + 0] + b0;
                float v1 = acc[mi][ni][half * 2 + 1] + b1;
                if (mode == 2) {
                    int b = m / SEQ;
                    int ss = m - b * SEQ;
                    int h = col0 >> 6;
                    int d = col0 & 63;
                    float2* dst = (float2*)&g_V[((size_t)(b * NHEADS + h) * SEQ + ss) * HDIM + d];
                    *dst = make_float2(v0, v1);
                } else {
                    float gm = gate[m];
                    float2* dst = (float2*)&outp[(size_t)m * DMODEL + col0];
                    *dst = make_float2(v0 * gm, v1 * gm);
                }
            }
        }
    }
}

// ---------------- K2: scores = Q K^T / 8, causal, 128x128, f32x2 -------------
__global__ __launch_bounds__(256) void scores_kernel()
{
    int kt = blockIdx.x;
    int qt = blockIdx.y;
    int bh = blockIdx.z;
    if (kt > qt) return;

    __shared__ float Qs[32][132];
    __shared__ float Ks[32][132];

    int tid = threadIdx.x;
    int tx = tid & 15;
    int ty = tid >> 4;
    const float* Qg = &g_Q[((size_t)bh * SEQ + qt * 128) * HDIM];
    const float* Kg = &g_K[((size_t)bh * SEQ + kt * 128) * HDIM];

    u64t acc2[4][8];
#pragma unroll
    for (int p = 0; p < 4; p++)
#pragma unroll
        for (int j = 0; j < 8; j++) acc2[p][j] = 0ull;

    int lr = tid >> 1;
    int lc = (tid & 1) * 16;

    for (int d0 = 0; d0 < HDIM; d0 += 32) {
#pragma unroll
        for (int t = 0; t < 4; t++) {
            float4 qv = *(const float4*)&Qg[(size_t)lr * HDIM + d0 + lc + t * 4];
            Qs[lc + t * 4 + 0][lr] = qv.x; Qs[lc + t * 4 + 1][lr] = qv.y;
            Qs[lc + t * 4 + 2][lr] = qv.z; Qs[lc + t * 4 + 3][lr] = qv.w;
            float4 kv = *(const float4*)&Kg[(size_t)lr * HDIM + d0 + lc + t * 4];
            Ks[lc + t * 4 + 0][lr] = kv.x; Ks[lc + t * 4 + 1][lr] = kv.y;
            Ks[lc + t * 4 + 2][lr] = kv.z; Ks[lc + t * 4 + 3][lr] = kv.w;
        }
        __syncthreads();
#pragma unroll
        for (int kk = 0; kk < 32; kk++) {
            u64t a2[4];
#pragma unroll
            for (int p = 0; p < 4; p++)
                a2[p] = *(const u64t*)&Qs[kk][ty * 8 + 2 * p];
            float b[8];
            *(float4*)&b[0] = *(const float4*)&Ks[kk][tx * 8 + 0];
            *(float4*)&b[4] = *(const float4*)&Ks[kk][tx * 8 + 4];
            u64t bb[8];
#pragma unroll
            for (int j = 0; j < 8; j++) bb[j] = dup2(b[j]);
#pragma unroll
            for (int p = 0; p < 4; p++)
#pragma unroll
                for (int j = 0; j < 8; j++) ffma2(acc2[p][j], a2[p], bb[j]);
        }
        __syncthreads();
    }

    const float scale = 0.125f;
    bool diag = (kt == qt);
#pragma unroll
    for (int p = 0; p < 4; p++) {
        float r0[8], r1[8];
#pragma unroll
        for (int j = 0; j < 8; j++) unpack2(acc2[p][j], r0[j], r1[j]);
#pragma unroll
        for (int half = 0; half < 2; half++) {
            int q = qt * 128 + ty * 8 + 2 * p + half;
            int kbase = kt * 128 + tx * 8;
            const float* rr = half ? r1 : r0;
            float vv[8];
#pragma unroll
            for (int j = 0; j < 8; j++) {
                float s = rr[j] * scale;
                vv[j] = (diag && (kbase + j > q)) ? -INFINITY : s;
            }
            float* dst = &g_P[((size_t)bh * SEQ + q) * SEQ + kbase];
            *(float4*)&dst[0] = *(float4*)&vv[0];
            *(float4*)&dst[4] = *(float4*)&vv[4];
        }
    }
}

// ---------------- K3: exact top-64 + softmax -> SPARSE (match_any hists) -----
__global__ __launch_bounds__(256) void topk_softmax_kernel()
{
    int row = blockIdx.x;
    int bh = row >> 11;
    int q = row & (SEQ - 1);
    size_t base = ((size_t)bh * SEQ + q) * SEQ;
    int L = q + 1;
    int L4 = (L + 3) & ~3;     // pad to float4; entries [L,L4) are -inf (diag mask)
    int tid = threadIdx.x;
    int lane = tid & 31;
    int warp = tid >> 5;

    __shared__ float sc[SEQ];
    __shared__ unsigned cand[SEQ];
    __shared__ unsigned hist[8][256];
    __shared__ unsigned sufS[256];
    __shared__ unsigned cntS[256];
    __shared__ unsigned warpTot[8];
    __shared__ unsigned ballots[8];
    __shared__ unsigned s_prefix;
    __shared__ int s_kk;
    __shared__ int s_cnt;
    __shared__ int s_keep;
    __shared__ float red[8];
    __shared__ float s_sum;
    __shared__ int s_pi[CAP];
    __shared__ float s_pv[CAP];

    bool doSel = (L > TOPK);

    for (int i = tid; i < 8 * 256; i += 256) ((unsigned*)hist)[i] = 0;
    if (tid == 0) { s_cnt = 0; s_keep = 0; }
    __syncthreads();

    // ---- pass 1: float4 load + max + per-warp match_any histogram -----------
    unsigned* histw = hist[warp];
    float m = -INFINITY;
    int niter = (L4 + 1023) >> 10;   // uniform trip count (1024 floats/iter)
    for (int it = 0; it < niter; it++) {
        int i0 = tid * 4 + (it << 10);
        bool valid = i0 < L4;
        float v[4] = {-INFINITY, -INFINITY, -INFINITY, -INFINITY};
        if (valid) {
            float4 v4 = *(const float4*)&g_P[base + i0];
            v[0] = v4.x; v[1] = v4.y; v[2] = v4.z; v[3] = v4.w;
            sc[i0 + 0] = v4.x; sc[i0 + 1] = v4.y;
            sc[i0 + 2] = v4.z; sc[i0 + 3] = v4.w;
            m = fmaxf(fmaxf(m, fmaxf(v4.x, v4.y)), fmaxf(v4.z, v4.w));
        }
        if (doSel) {
#pragma unroll
            for (int j = 0; j < 4; j++) {
                unsigned u = __float_as_uint(v[j]);
                unsigned key = (u & 0x80000000u) ? ~u : (u | 0x80000000u);
                int bin = valid ? (int)(key >> 24) : 300;
                unsigned grp = __match_any_sync(0xFFFFFFFFu, bin);
                if (valid && lane == (__ffs(grp) - 1))
                    histw[bin] += __popc(grp);
            }
        }
    }
#pragma unroll
    for (int off = 16; off; off >>= 1) m = fmaxf(m, __shfl_xor_sync(0xFFFFFFFFu, m, off));
    if (lane == 0) red[warp] = m;
    __syncthreads();
    {
        float mm = red[0];
#pragma unroll
        for (int w = 1; w < 8; w++) mm = fmaxf(mm, red[w]);
        m = mm;
    }

    float thresh = -INFINITY;
    if (doSel) {
        // ---- pass-1 digit select (bins already built; padding in bin 0 only,
        //      never selected since >=65 finite keys live in higher bins) -----
        unsigned cnt = 0;
#pragma unroll
        for (int w = 0; w < 8; w++) cnt += hist[w][tid];
        unsigned s = cnt;
#pragma unroll
        for (int off = 1; off < 32; off <<= 1) {
            unsigned t = __shfl_down_sync(0xFFFFFFFFu, s, off);
            if (lane + off < 32) s += t;
        }
        if (lane == 0) warpTot[warp] = s;
        __syncthreads();
        unsigned hi = 0;
        for (int w2 = warp + 1; w2 < 8; w2++) hi += warpTot[w2];
        unsigned S = s + hi;
        sufS[tid] = S;
        cntS[tid] = cnt;
        unsigned bal = __ballot_sync(0xFFFFFFFFu, S >= (unsigned)TOPK);
        if (lane == 0) ballots[warp] = bal;
        __syncthreads();
        if (tid == 0) {
            int sel = 0;
            for (int w = 7; w >= 0; w--) {
                if (ballots[w]) { sel = w * 32 + (31 - __clz(ballots[w])); break; }
            }
            s_kk = TOPK - (int)(sufS[sel] - cntS[sel]);
            s_prefix = (unsigned)sel << 24;
        }
        __syncthreads();
        unsigned prefix = s_prefix;
        unsigned selTop = prefix >> 24;

        // ---- compact candidates (keys sharing selected top byte) ------------
        for (int i = tid; i < L; i += 256) {
            unsigned u = __float_as_uint(sc[i]);
            unsigned key = (u & 0x80000000u) ? ~u : (u | 0x80000000u);
            if ((key >> 24) == selTop) {
                int idx = atomicAdd(&s_cnt, 1);
                cand[idx] = key;
            }
        }
        __syncthreads();
        int C = s_cnt;
        unsigned himask = 0xFF000000u;
        int kk = s_kk;

        // ---- 3 radix passes over candidates only (atomics; C is small) ------
        for (int p = 16; p >= 0; p -= 8) {
            for (int i = tid; i < 8 * 256; i += 256) ((unsigned*)hist)[i] = 0;
            __syncthreads();
            for (int i = tid; i < C; i += 256) {
                unsigned key = cand[i];
                if ((key & himask) == prefix)
                    atomicAdd(&hist[warp][(key >> p) & 0xFFu], 1u);
            }
            __syncthreads();
            unsigned c2 = 0;
#pragma unroll
            for (int w = 0; w < 8; w++) c2 += hist[w][tid];
            unsigned s2 = c2;
#pragma unroll
            for (int off = 1; off < 32; off <<= 1) {
                unsigned t = __shfl_down_sync(0xFFFFFFFFu, s2, off);
                if (lane + off < 32) s2 += t;
            }
            if (lane == 0) warpTot[warp] = s2;
            __syncthreads();
            unsigned hi2 = 0;
            for (int w2 = warp + 1; w2 < 8; w2++) hi2 += warpTot[w2];
            unsigned S2 = s2 + hi2;
            sufS[tid] = S2;
            cntS[tid] = c2;
            unsigned bal2 = __ballot_sync(0xFFFFFFFFu, S2 >= (unsigned)kk);
            if (lane == 0) ballots[warp] = bal2;
            __syncthreads();
            if (tid == 0) {
                int sel = 0;
                for (int w = 7; w >= 0; w--) {
                    if (ballots[w]) { sel = w * 32 + (31 - __clz(ballots[w])); break; }
                }
                s_kk = s_kk - (int)(sufS[sel] - cntS[sel]);
                s_prefix = prefix | ((unsigned)sel << p);
            }
            __syncthreads();
            prefix = s_prefix;
            kk = s_kk;
            himask |= (0xFFu << p);
            __syncthreads();
        }
        unsigned key = prefix;
        unsigned u = (key & 0x80000000u) ? (key & 0x7FFFFFFFu) : ~key;
        thresh = __uint_as_float(u);
    }

    // ---- compact kept entries (v >= thresh, i < L) + unnormalized exp -------
    for (int i = tid; i < L; i += 256) {
        float v = sc[i];
        if (v >= thresh) {
            int pos = atomicAdd(&s_keep, 1);
            if (pos < CAP) {
                s_pi[pos] = i;
                s_pv[pos] = __expf(v - m);
            }
        }
    }
    __syncthreads();
    int cnt = min(s_keep, CAP);

    if (warp == 0) {
        float ss = 0.0f;
        for (int j = lane; j < cnt; j += 32) ss += s_pv[j];
#pragma unroll
        for (int off = 16; off; off >>= 1) ss += __shfl_xor_sync(0xFFFFFFFFu, ss, off);
        if (lane == 0) s_sum = ss;
    }
    __syncthreads();
    float inv = 1.0f / s_sum;

    if (tid < cnt) {
        g_PI[(size_t)row * CAP + tid] = s_pi[tid];
        g_PV[(size_t)row * CAP + tid] = s_pv[tid] * inv;
    }
    if (tid == 0) g_CNT[row] = cnt;
}

// ---------------- K4: sparse O = P @ V (one warp per query row, fp32) --------
__global__ __launch_bounds__(256) void av_sparse_kernel()
{
    int row = blockIdx.x * 8 + (threadIdx.x >> 5);
    int lane = threadIdx.x & 31;
    int bh = row >> 11;
    int s = row & (SEQ - 1);
    int b = bh >> 4;
    int h = bh & 15;

    int cnt = g_CNT[row];
    const float* Vb = &g_V[(size_t)bh * SEQ * HDIM];
    const int* PI = &g_PI[(size_t)row * CAP];
    const float* PV = &g_PV[(size_t)row * CAP];

    float a0 = 0.0f, a1 = 0.0f;
    for (int c = 0; c < cnt; c += 32) {
        int myIdx = 0;
        float myP = 0.0f;
        if (c + lane < cnt) {
            myIdx = PI[c + lane];
            myP = PV[c + lane];
        }
        int nn = min(32, cnt - c);
#pragma unroll 8
        for (int jj = 0; jj < nn; jj++) {
            int idx = __shfl_sync(0xFFFFFFFFu, myIdx, jj);
            float p = __shfl_sync(0xFFFFFFFFu, myP, jj);
            float2 v = *(const float2*)&Vb[(size_t)idx * HDIM + lane * 2];
            a0 = fmaf(p, v.x, a0);
            a1 = fmaf(p, v.y, a1);
        }
    }

    float2* dst = (float2*)&g_O[(size_t)(b * SEQ + s) * DMODEL + h * HDIM + lane * 2];
    *dst = make_float2(a0, a1);
}

// ---------------- launch ------------------------------------------------------
extern "C" void kernel_launch(void* const* d_in, const int* in_sizes, int n_in,
                              void* d_out, int out_size)
{
    const float* h_ssm = (const float*)d_in[0];
    const float* gate  = (const float*)d_in[1];
    const float* Wq = (const float*)d_in[2];
    const float* bq = (const float*)d_in[3];
    const float* Wk = (const float*)d_in[4];
    const float* bk = (const float*)d_in[5];
    const float* Wv = (const float*)d_in[6];
    const float* bv = (const float*)d_in[7];
    const float* Wo = (const float*)d_in[8];
    const float* bo = (const float*)d_in[9];
    float* out = (float*)d_out;

    dim3 gProj(DMODEL / 128, NROWS / 128);          // (8, 32)
    gemm_kernel<<<gProj, 256>>>(h_ssm, Wq, bq, 0);
    gemm_kernel<<<gProj, 256>>>(h_ssm, Wk, bk, 1);
    gemm_bf16_kernel<<<gProj, 256>>>(h_ssm, Wv, bv, nullptr, nullptr, 2);

    scores_kernel<<<dim3(SEQ / 128, SEQ / 128, BH), 256>>>();
    topk_softmax_kernel<<<dim3(BH * SEQ), 256>>>();
    av_sparse_kernel<<<dim3(BH * SEQ / 8), 256>>>();

    gemm_bf16_kernel<<<gProj, 256>>>(nullptr, Wo, bo, out, gate, 3);
}

// round 15
// speedup vs baseline: 1.1631x; 1.0249x over previous
#include <cuda_runtime.h>
#include <cuda_bf16.h>
#include <math.h>
#include <stdint.h>

// Problem constants
#define BATCH 2
#define SEQ 2048
#define DMODEL 1024
#define NHEADS 16
#define HDIM 64
#define TOPK 64
#define NROWS (BATCH * SEQ)          // 4096
#define BH (BATCH * NHEADS)          // 32
#define CAP 80                       // kept-slot capacity (64 + tie headroom)

// ---------------- scratch (device globals; allocation-free rule) -------------
__device__ float g_Q[(size_t)BH * SEQ * HDIM];   // [bh, s, d] 16MB
__device__ float g_K[(size_t)BH * SEQ * HDIM];   // 16MB
__device__ float g_V[(size_t)BH * SEQ * HDIM];   // 16MB
__device__ float g_P[(size_t)BH * SEQ * SEQ];    // raw scores, 512MB
__device__ int   g_PI[(size_t)BH * SEQ * CAP];   // kept key indices
__device__ float g_PV[(size_t)BH * SEQ * CAP];   // kept normalized probs
__device__ int   g_CNT[(size_t)BH * SEQ];        // kept count per row
__device__ float g_O[(size_t)NROWS * DMODEL];    // attn output pre-Wo, 16MB

// ---------------- f32x2 packed-fma helpers ------------------------------------
typedef unsigned long long u64t;
__device__ __forceinline__ u64t dup2(float x) {
    u64t d;
    unsigned u = __float_as_uint(x);
    asm("mov.b64 %0, {%1, %1};" : "=l"(d) : "r"(u));
    return d;
}
__device__ __forceinline__ void ffma2(u64t& c, u64t a, u64t b) {
    asm("fma.rn.f32x2 %0, %1, %2, %0;" : "+l"(c) : "l"(a), "l"(b));
}
__device__ __forceinline__ void unpack2(u64t d, float& x, float& y) {
    unsigned lo, hi;
    asm("mov.b64 {%0, %1}, %2;" : "=r"(lo), "=r"(hi) : "l"(d));
    x = __uint_as_float(lo);
    y = __uint_as_float(hi);
}

// ---------------- tensor-core helpers ----------------------------------------
__device__ __forceinline__ uint32_t smem_u32(const void* p) {
    return (uint32_t)__cvta_generic_to_shared(p);
}
__device__ __forceinline__ void ldmA4(uint32_t addr, uint32_t& r0, uint32_t& r1,
                                      uint32_t& r2, uint32_t& r3) {
    asm volatile("ldmatrix.sync.aligned.m8n8.x4.shared.b16 {%0,%1,%2,%3}, [%4];"
                 : "=r"(r0), "=r"(r1), "=r"(r2), "=r"(r3) : "r"(addr));
}
__device__ __forceinline__ void ldmB2t(uint32_t addr, uint32_t& r0, uint32_t& r1) {
    asm volatile("ldmatrix.sync.aligned.m8n8.x2.trans.shared.b16 {%0,%1}, [%2];"
                 : "=r"(r0), "=r"(r1) : "r"(addr));
}
__device__ __forceinline__ void mma16816(float* c, uint32_t a0, uint32_t a1,
                                         uint32_t a2, uint32_t a3,
                                         uint32_t b0, uint32_t b1) {
    asm volatile(
        "mma.sync.aligned.m16n8k16.row.col.f32.bf16.bf16.f32 "
        "{%0,%1,%2,%3}, {%4,%5,%6,%7}, {%8,%9}, {%0,%1,%2,%3};"
        : "+f"(c[0]), "+f"(c[1]), "+f"(c[2]), "+f"(c[3])
        : "r"(a0), "r"(a1), "r"(a2), "r"(a3), "r"(b0), "r"(b1));
}
__device__ __forceinline__ void split_bf16(float x, __nv_bfloat16& hi, __nv_bfloat16& lo) {
    hi = __float2bfloat16(x);
    lo = __float2bfloat16(x - __bfloat162float(hi));
}

// ---------------- K1: fused Q+K projection (blockIdx.z selects) --------------
__global__ __launch_bounds__(256) void qk_proj_kernel(
    const float* __restrict__ A,
    const float* __restrict__ Wq,
    const float* __restrict__ bq,
    const float* __restrict__ Wk,
    const float* __restrict__ bk)
{
    __shared__ float As[16][132];
    __shared__ float Bs[16][128];

    const int K = DMODEL;
    const int NC = DMODEL;
    int tid = threadIdx.x;
    int tx = tid & 15;
    int ty = tid >> 4;
    int rowTile = blockIdx.y * 128;
    int colTile = blockIdx.x * 128;
    int mode = blockIdx.z;                       // 0 -> Q, 1 -> K

    const float* W = (mode == 0) ? Wq : Wk;
    const float* bias = (mode == 0) ? bq : bk;
    float* Op = (mode == 0) ? g_Q : g_K;

    int ar = tid >> 1;
    int ac8 = (tid & 1) * 8;
    int br = tid >> 4;
    int bc8 = (tid & 15) * 8;

    u64t acc2[4][8];
#pragma unroll
    for (int p = 0; p < 4; p++)
#pragma unroll
        for (int j = 0; j < 8; j++) acc2[p][j] = 0ull;

    const float* aptr = &A[(size_t)(rowTile + ar) * K];
    const float* bptr = &W[(size_t)colTile + bc8];

    {
        float4 a0 = *(const float4*)&aptr[ac8 + 0];
        float4 a1 = *(const float4*)&aptr[ac8 + 4];
        As[ac8 + 0][ar] = a0.x; As[ac8 + 1][ar] = a0.y;
        As[ac8 + 2][ar] = a0.z; As[ac8 + 3][ar] = a0.w;
        As[ac8 + 4][ar] = a1.x; As[ac8 + 5][ar] = a1.y;
        As[ac8 + 6][ar] = a1.z; As[ac8 + 7][ar] = a1.w;
        *(float4*)&Bs[br][bc8 + 0] = *(const float4*)&bptr[(size_t)br * NC + 0];
        *(float4*)&Bs[br][bc8 + 4] = *(const float4*)&bptr[(size_t)br * NC + 4];
    }
    __syncthreads();

    for (int k0 = 0; k0 < K; k0 += 16) {
        bool has = (k0 + 16) < K;
        float4 pa0, pa1, pb0, pb1;
        if (has) {
            pa0 = *(const float4*)&aptr[k0 + 16 + ac8 + 0];
            pa1 = *(const float4*)&aptr[k0 + 16 + ac8 + 4];
            pb0 = *(const float4*)&bptr[(size_t)(k0 + 16 + br) * NC + 0];
            pb1 = *(const float4*)&bptr[(size_t)(k0 + 16 + br) * NC + 4];
        }
#pragma unroll
        for (int kk = 0; kk < 16; kk++) {
            u64t a2[4];
#pragma unroll
            for (int p = 0; p < 4; p++)
                a2[p] = *(const u64t*)&As[kk][ty * 8 + 2 * p];
            float b[8];
            *(float4*)&b[0] = *(const float4*)&Bs[kk][tx * 8 + 0];
            *(float4*)&b[4] = *(const float4*)&Bs[kk][tx * 8 + 4];
            u64t bb[8];
#pragma unroll
            for (int j = 0; j < 8; j++) bb[j] = dup2(b[j]);
#pragma unroll
            for (int p = 0; p < 4; p++)
#pragma unroll
                for (int j = 0; j < 8; j++) ffma2(acc2[p][j], a2[p], bb[j]);
        }
        __syncthreads();
        if (has) {
            As[ac8 + 0][ar] = pa0.x; As[ac8 + 1][ar] = pa0.y;
            As[ac8 + 2][ar] = pa0.z; As[ac8 + 3][ar] = pa0.w;
            As[ac8 + 4][ar] = pa1.x; As[ac8 + 5][ar] = pa1.y;
            As[ac8 + 6][ar] = pa1.z; As[ac8 + 7][ar] = pa1.w;
            *(float4*)&Bs[br][bc8 + 0] = pb0;
            *(float4*)&Bs[br][bc8 + 4] = pb1;
            __syncthreads();
        }
    }

#pragma unroll
    for (int p = 0; p < 4; p++) {
        float r0[8], r1[8];
#pragma unroll
        for (int j = 0; j < 8; j++) unpack2(acc2[p][j], r0[j], r1[j]);
#pragma unroll
        for (int half = 0; half < 2; half++) {
            int m = rowTile + ty * 8 + 2 * p + half;
            int b = m / SEQ;
            int s = m - b * SEQ;
            const float* rr = half ? r1 : r0;
#pragma unroll
            for (int j = 0; j < 8; j++) {
                int n = colTile + tx * 8 + j;
                int h = n >> 6;
                int d = n & 63;
                Op[((size_t)(b * NHEADS + h) * SEQ + s) * HDIM + d] = rr[j] + bias[n];
            }
        }
    }
}

// ---------------- K1b: 128x128 split-bf16 tensor-core GEMM -------------------
__global__ __launch_bounds__(256) void gemm_bf16_kernel(
    const float* __restrict__ A,
    const float* __restrict__ W,
    const float* __restrict__ bias,
    float* __restrict__ outp,
    const float* __restrict__ gate,
    int mode)
{
    __shared__ __nv_bfloat16 Ahi[128][40], Alo[128][40];
    __shared__ __nv_bfloat16 Bhi[32][136], Blo[32][136];

    const int K = DMODEL;
    const int NC = DMODEL;
    int tid = threadIdx.x;
    int lane = tid & 31;
    int wid = tid >> 5;
    int wm = wid & 1;
    int wn = wid >> 1;
    int rowTile = blockIdx.y * 128;
    int colTile = blockIdx.x * 128;

    const float* Ap = (mode == 3) ? g_O : A;

    int ar = tid >> 1, ac = (tid & 1) * 16;
    int br = tid >> 3, bc = (tid & 7) * 16;
    const float* aptr = &Ap[(size_t)(rowTile + ar) * K + ac];
    const float* bptr = &W[(size_t)br * NC + colTile + bc];

    float acc[4][4][4];
#pragma unroll
    for (int mi = 0; mi < 4; mi++)
#pragma unroll
        for (int ni = 0; ni < 4; ni++)
#pragma unroll
            for (int r = 0; r < 4; r++) acc[mi][ni][r] = 0.0f;

    float4 pa[4], pb[4];
#pragma unroll
    for (int t = 0; t < 4; t++) {
        pa[t] = *(const float4*)&aptr[t * 4];
        pb[t] = *(const float4*)&bptr[t * 4];
    }
#pragma unroll
    for (int t = 0; t < 4; t++) {
        float v[4] = {pa[t].x, pa[t].y, pa[t].z, pa[t].w};
        __nv_bfloat16 h0, l0, h1, l1;
        split_bf16(v[0], h0, l0); split_bf16(v[1], h1, l1);
        *(__nv_bfloat162*)&Ahi[ar][ac + t * 4] = __nv_bfloat162(h0, h1);
        *(__nv_bfloat162*)&Alo[ar][ac + t * 4] = __nv_bfloat162(l0, l1);
        split_bf16(v[2], h0, l0); split_bf16(v[3], h1, l1);
        *(__nv_bfloat162*)&Ahi[ar][ac + t * 4 + 2] = __nv_bfloat162(h0, h1);
        *(__nv_bfloat162*)&Alo[ar][ac + t * 4 + 2] = __nv_bfloat162(l0, l1);
        float w[4] = {pb[t].x, pb[t].y, pb[t].z, pb[t].w};
        split_bf16(w[0], h0, l0); split_bf16(w[1], h1, l1);
        *(__nv_bfloat162*)&Bhi[br][bc + t * 4] = __nv_bfloat162(h0, h1);
        *(__nv_bfloat162*)&Blo[br][bc + t * 4] = __nv_bfloat162(l0, l1);
        split_bf16(w[2], h0, l0); split_bf16(w[3], h1, l1);
        *(__nv_bfloat162*)&Bhi[br][bc + t * 4 + 2] = __nv_bfloat162(h0, h1);
        *(__nv_bfloat162*)&Blo[br][bc + t * 4 + 2] = __nv_bfloat162(l0, l1);
    }
    __syncthreads();

    for (int s = 0; s < K / 32; s++) {
        bool has = (s + 1) < K / 32;
        if (has) {
            int k0 = (s + 1) * 32;
#pragma unroll
            for (int t = 0; t < 4; t++) {
                pa[t] = *(const float4*)&aptr[k0 + t * 4];
                pb[t] = *(const float4*)&bptr[(size_t)k0 * NC + t * 4];
            }
        }
#pragma unroll
        for (int ks = 0; ks < 2; ks++) {
            int kk = ks * 16;
            uint32_t bhr[4][2], blr[4][2];
#pragma unroll
            for (int ni = 0; ni < 4; ni++) {
                ldmB2t(smem_u32(&Bhi[kk + (lane & 15)][wn * 32 + ni * 8]), bhr[ni][0], bhr[ni][1]);
                ldmB2t(smem_u32(&Blo[kk + (lane & 15)][wn * 32 + ni * 8]), blr[ni][0], blr[ni][1]);
            }
#pragma unroll
            for (int mi = 0; mi < 4; mi++) {
                int arow = wm * 64 + mi * 16 + (lane & 15);
                int acol = kk + ((lane >> 4) << 3);
                uint32_t ah0, ah1, ah2, ah3, al0, al1, al2, al3;
                ldmA4(smem_u32(&Ahi[arow][acol]), ah0, ah1, ah2, ah3);
                ldmA4(smem_u32(&Alo[arow][acol]), al0, al1, al2, al3);
#pragma unroll
                for (int ni = 0; ni < 4; ni++) {
                    mma16816(acc[mi][ni], ah0, ah1, ah2, ah3, bhr[ni][0], bhr[ni][1]);
                    mma16816(acc[mi][ni], al0, al1, al2, al3, bhr[ni][0], bhr[ni][1]);
                    mma16816(acc[mi][ni], ah0, ah1, ah2, ah3, blr[ni][0], blr[ni][1]);
                }
            }
        }
        __syncthreads();
        if (has) {
#pragma unroll
            for (int t = 0; t < 4; t++) {
                float v[4] = {pa[t].x, pa[t].y, pa[t].z, pa[t].w};
                __nv_bfloat16 h0, l0, h1, l1;
                split_bf16(v[0], h0, l0); split_bf16(v[1], h1, l1);
                *(__nv_bfloat162*)&Ahi[ar][ac + t * 4] = __nv_bfloat162(h0, h1);
                *(__nv_bfloat162*)&Alo[ar][ac + t * 4] = __nv_bfloat162(l0, l1);
                split_bf16(v[2], h0, l0); split_bf16(v[3], h1, l1);
                *(__nv_bfloat162*)&Ahi[ar][ac + t * 4 + 2] = __nv_bfloat162(h0, h1);
                *(__nv_bfloat162*)&Alo[ar][ac + t * 4 + 2] = __nv_bfloat162(l0, l1);
                float w[4] = {pb[t].x, pb[t].y, pb[t].z, pb[t].w};
                split_bf16(w[0], h0, l0); split_bf16(w[1], h1, l1);
                *(__nv_bfloat162*)&Bhi[br][bc + t * 4] = __nv_bfloat162(h0, h1);
                *(__nv_bfloat162*)&Blo[br][bc + t * 4] = __nv_bfloat162(l0, l1);
                split_bf16(w[2], h0, l0); split_bf16(w[3], h1, l1);
                *(__nv_bfloat162*)&Bhi[br][bc + t * 4 + 2] = __nv_bfloat162(h0, h1);
                *(__nv_bfloat162*)&Blo[br][bc + t * 4 + 2] = __nv_bfloat162(l0, l1);
            }
            __syncthreads();
        }
    }

#pragma unroll
    for (int mi = 0; mi < 4; mi++) {
#pragma unroll
        for (int ni = 0; ni < 4; ni++) {
            int row0 = rowTile + wm * 64 + mi * 16 + (lane >> 2);
            int col0 = colTile + wn * 32 + ni * 8 + (lane & 3) * 2;
            float b0 = bias[col0], b1 = bias[col0 + 1];
#pragma unroll
            for (int half = 0; half < 2; half++) {
                int m = row0 + half * 8;
                float v0 = acc[mi][ni][half * 2 + 0] + b0;
                float v1 = acc[mi][ni][half * 2 + 1] + b1;
                if (mode == 2) {
                    int b = m / SEQ;
                    int ss = m - b * SEQ;
                    int h = col0 >> 6;
                    int d = col0 & 63;
                    float2* dst = (float2*)&g_V[((size_t)(b * NHEADS + h) * SEQ + ss) * HDIM + d];
                    *dst = make_float2(v0, v1);
                } else {
                    float gm = gate[m];
                    float2* dst = (float2*)&outp[(size_t)m * DMODEL + col0];
                    *dst = make_float2(v0 * gm, v1 * gm);
                }
            }
        }
    }
}

// ---------------- K2: scores = Q K^T / 8, causal, 128x128, f32x2, v3 ---------
// Single 64-deep smem slab (dynamic), one sync, uninterrupted 64-kk FMA stream.
#define SCORES_SMEM (2 * 64 * 132 * 4)   // 67584 bytes

extern __shared__ float dynsmem[];

__global__ __launch_bounds__(256) void scores_kernel()
{
    int kt = blockIdx.x;
    int qt = blockIdx.y;
    int bh = blockIdx.z;
    if (kt > qt) return;

    float* Qs = dynsmem;                  // [64][132] transposed [d][row]
    float* Ks = dynsmem + 64 * 132;       // [64][132]

    int tid = threadIdx.x;
    int tx = tid & 15;
    int ty = tid >> 4;
    const float* Qg = &g_Q[((size_t)bh * SEQ + qt * 128) * HDIM];
    const float* Kg = &g_K[((size_t)bh * SEQ + kt * 128) * HDIM];

    u64t acc2[4][8];
#pragma unroll
    for (int p = 0; p < 4; p++)
#pragma unroll
        for (int j = 0; j < 8; j++) acc2[p][j] = 0ull;

    int lr = tid >> 1;
    int lc = (tid & 1) * 16;

    // load full 64-d slab (both halves), transposed
#pragma unroll
    for (int d0 = 0; d0 < HDIM; d0 += 32) {
#pragma unroll
        for (int t = 0; t < 4; t++) {
            int dd = d0 + lc + t * 4;
            float4 qv = *(const float4*)&Qg[(size_t)lr * HDIM + dd];
            Qs[(dd + 0) * 132 + lr] = qv.x; Qs[(dd + 1) * 132 + lr] = qv.y;
            Qs[(dd + 2) * 132 + lr] = qv.z; Qs[(dd + 3) * 132 + lr] = qv.w;
            float4 kv = *(const float4*)&Kg[(size_t)lr * HDIM + dd];
            Ks[(dd + 0) * 132 + lr] = kv.x; Ks[(dd + 1) * 132 + lr] = kv.y;
            Ks[(dd + 2) * 132 + lr] = kv.z; Ks[(dd + 3) * 132 + lr] = kv.w;
        }
    }
    __syncthreads();

#pragma unroll 16
    for (int kk = 0; kk < HDIM; kk++) {
        u64t a2[4];
#pragma unroll
        for (int p = 0; p < 4; p++)
            a2[p] = *(const u64t*)&Qs[kk * 132 + ty * 8 + 2 * p];
        float b[8];
        *(float4*)&b[0] = *(const float4*)&Ks[kk * 132 + tx * 8 + 0];
        *(float4*)&b[4] = *(const float4*)&Ks[kk * 132 + tx * 8 + 4];
        u64t bb[8];
#pragma unroll
        for (int j = 0; j < 8; j++) bb[j] = dup2(b[j]);
#pragma unroll
        for (int p = 0; p < 4; p++)
#pragma unroll
            for (int j = 0; j < 8; j++) ffma2(acc2[p][j], a2[p], bb[j]);
    }

    const float scale = 0.125f;
    bool diag = (kt == qt);
#pragma unroll
    for (int p = 0; p < 4; p++) {
        float r0[8], r1[8];
#pragma unroll
        for (int j = 0; j < 8; j++) unpack2(acc2[p][j], r0[j], r1[j]);
#pragma unroll
        for (int half = 0; half < 2; half++) {
            int q = qt * 128 + ty * 8 + 2 * p + half;
            int kbase = kt * 128 + tx * 8;
            const float* rr = half ? r1 : r0;
            float vv[8];
#pragma unroll
            for (int j = 0; j < 8; j++) {
                float s = rr[j] * scale;
                vv[j] = (diag && (kbase + j > q)) ? -INFINITY : s;
            }
            float* dst = &g_P[((size_t)bh * SEQ + q) * SEQ + kbase];
            *(float4*)&dst[0] = *(float4*)&vv[0];
            *(float4*)&dst[4] = *(float4*)&vv[4];
        }
    }
}

// ---------------- K3: exact top-64 + softmax -> SPARSE (match_any hists) -----
__global__ __launch_bounds__(256) void topk_softmax_kernel()
{
    int row = blockIdx.x;
    int bh = row >> 11;
    int q = row & (SEQ - 1);
    size_t base = ((size_t)bh * SEQ + q) * SEQ;
    int L = q + 1;
    int L4 = (L + 3) & ~3;     // pad to float4; entries [L,L4) are -inf (diag mask)
    int tid = threadIdx.x;
    int lane = tid & 31;
    int warp = tid >> 5;

    __shared__ float sc[SEQ];
    __shared__ unsigned cand[SEQ];
    __shared__ unsigned hist[8][256];
    __shared__ unsigned sufS[256];
    __shared__ unsigned cntS[256];
    __shared__ unsigned warpTot[8];
    __shared__ unsigned ballots[8];
    __shared__ unsigned s_prefix;
    __shared__ int s_kk;
    __shared__ int s_cnt;
    __shared__ int s_keep;
    __shared__ float red[8];
    __shared__ float s_sum;
    __shared__ int s_pi[CAP];
    __shared__ float s_pv[CAP];

    bool doSel = (L > TOPK);

    for (int i = tid; i < 8 * 256; i += 256) ((unsigned*)hist)[i] = 0;
    if (tid == 0) { s_cnt = 0; s_keep = 0; }
    __syncthreads();

    unsigned* histw = hist[warp];
    float m = -INFINITY;
    int niter = (L4 + 1023) >> 10;
    for (int it = 0; it < niter; it++) {
        int i0 = tid * 4 + (it << 10);
        bool valid = i0 < L4;
        float v[4] = {-INFINITY, -INFINITY, -INFINITY, -INFINITY};
        if (valid) {
            float4 v4 = *(const float4*)&g_P[base + i0];
            v[0] = v4.x; v[1] = v4.y; v[2] = v4.z; v[3] = v4.w;
            sc[i0 + 0] = v4.x; sc[i0 + 1] = v4.y;
            sc[i0 + 2] = v4.z; sc[i0 + 3] = v4.w;
            m = fmaxf(fmaxf(m, fmaxf(v4.x, v4.y)), fmaxf(v4.z, v4.w));
        }
        if (doSel) {
#pragma unroll
            for (int j = 0; j < 4; j++) {
                unsigned u = __float_as_uint(v[j]);
                unsigned key = (u & 0x80000000u) ? ~u : (u | 0x80000000u);
                int bin = valid ? (int)(key >> 24) : 300;
                unsigned grp = __match_any_sync(0xFFFFFFFFu, bin);
                if (valid && lane == (__ffs(grp) - 1))
                    histw[bin] += __popc(grp);
            }
        }
    }
#pragma unroll
    for (int off = 16; off; off >>= 1) m = fmaxf(m, __shfl_xor_sync(0xFFFFFFFFu, m, off));
    if (lane == 0) red[warp] = m;
    __syncthreads();
    {
        float mm = red[0];
#pragma unroll
        for (int w = 1; w < 8; w++) mm = fmaxf(mm, red[w]);
        m = mm;
    }

    float thresh = -INFINITY;
    if (doSel) {
        unsigned cnt = 0;
#pragma unroll
        for (int w = 0; w < 8; w++) cnt += hist[w][tid];
        unsigned s = cnt;
#pragma unroll
        for (int off = 1; off < 32; off <<= 1) {
            unsigned t = __shfl_down_sync(0xFFFFFFFFu, s, off);
            if (lane + off < 32) s += t;
        }
        if (lane == 0) warpTot[warp] = s;
        __syncthreads();
        unsigned hi = 0;
        for (int w2 = warp + 1; w2 < 8; w2++) hi += warpTot[w2];
        unsigned S = s + hi;
        sufS[tid] = S;
        cntS[tid] = cnt;
        unsigned bal = __ballot_sync(0xFFFFFFFFu, S >= (unsigned)TOPK);
        if (lane == 0) ballots[warp] = bal;
        __syncthreads();
        if (tid == 0) {
            int sel = 0;
            for (int w = 7; w >= 0; w--) {
                if (ballots[w]) { sel = w * 32 + (31 - __clz(ballots[w])); break; }
            }
            s_kk = TOPK - (int)(sufS[sel] - cntS[sel]);
            s_prefix = (unsigned)sel << 24;
        }
        __syncthreads();
        unsigned prefix = s_prefix;
        unsigned selTop = prefix >> 24;

        for (int i = tid; i < L; i += 256) {
            unsigned u = __float_as_uint(sc[i]);
            unsigned key = (u & 0x80000000u) ? ~u : (u | 0x80000000u);
            if ((key >> 24) == selTop) {
                int idx = atomicAdd(&s_cnt, 1);
                cand[idx] = key;
            }
        }
        __syncthreads();
        int C = s_cnt;
        unsigned himask = 0xFF000000u;
        int kk = s_kk;

        for (int p = 16; p >= 0; p -= 8) {
            for (int i = tid; i < 8 * 256; i += 256) ((unsigned*)hist)[i] = 0;
            __syncthreads();
            for (int i = tid; i < C; i += 256) {
                unsigned key = cand[i];
                if ((key & himask) == prefix)
                    atomicAdd(&hist[warp][(key >> p) & 0xFFu], 1u);
            }
            __syncthreads();
            unsigned c2 = 0;
#pragma unroll
            for (int w = 0; w < 8; w++) c2 += hist[w][tid];
            unsigned s2 = c2;
#pragma unroll
            for (int off = 1; off < 32; off <<= 1) {
                unsigned t = __shfl_down_sync(0xFFFFFFFFu, s2, off);
                if (lane + off < 32) s2 += t;
            }
            if (lane == 0) warpTot[warp] = s2;
            __syncthreads();
            unsigned hi2 = 0;
            for (int w2 = warp + 1; w2 < 8; w2++) hi2 += warpTot[w2];
            unsigned S2 = s2 + hi2;
            sufS[tid] = S2;
            cntS[tid] = c2;
            unsigned bal2 = __ballot_sync(0xFFFFFFFFu, S2 >= (unsigned)kk);
            if (lane == 0) ballots[warp] = bal2;
            __syncthreads();
            if (tid == 0) {
                int sel = 0;
                for (int w = 7; w >= 0; w--) {
                    if (ballots[w]) { sel = w * 32 + (31 - __clz(ballots[w])); break; }
                }
                s_kk = s_kk - (int)(sufS[sel] - cntS[sel]);
                s_prefix = prefix | ((unsigned)sel << p);
            }
            __syncthreads();
            prefix = s_prefix;
            kk = s_kk;
            himask |= (0xFFu << p);
            __syncthreads();
        }
        unsigned key = prefix;
        unsigned u = (key & 0x80000000u) ? (key & 0x7FFFFFFFu) : ~key;
        thresh = __uint_as_float(u);
    }

    for (int i = tid; i < L; i += 256) {
        float v = sc[i];
        if (v >= thresh) {
            int pos = atomicAdd(&s_keep, 1);
            if (pos < CAP) {
                s_pi[pos] = i;
                s_pv[pos] = __expf(v - m);
            }
        }
    }
    __syncthreads();
    int cnt = min(s_keep, CAP);

    if (warp == 0) {
        float ss = 0.0f;
        for (int j = lane; j < cnt; j += 32) ss += s_pv[j];
#pragma unroll
        for (int off = 16; off; off >>= 1) ss += __shfl_xor_sync(0xFFFFFFFFu, ss, off);
        if (lane == 0) s_sum = ss;
    }
    __syncthreads();
    float inv = 1.0f / s_sum;

    if (tid < cnt) {
        g_PI[(size_t)row * CAP + tid] = s_pi[tid];
        g_PV[(size_t)row * CAP + tid] = s_pv[tid] * inv;
    }
    if (tid == 0) g_CNT[row] = cnt;
}

// ---------------- K4: sparse O = P @ V (one warp per query row, fp32) --------
__global__ __launch_bounds__(256) void av_sparse_kernel()
{
    int row = blockIdx.x * 8 + (threadIdx.x >> 5);
    int lane = threadIdx.x & 31;
    int bh = row >> 11;
    int s = row & (SEQ - 1);
    int b = bh >> 4;
    int h = bh & 15;

    int cnt = g_CNT[row];
    const float* Vb = &g_V[(size_t)bh * SEQ * HDIM];
    const int* PI = &g_PI[(size_t)row * CAP];
    const float* PV = &g_PV[(size_t)row * CAP];

    float a0 = 0.0f, a1 = 0.0f;
    for (int c = 0; c < cnt; c += 32) {
        int myIdx = 0;
        float myP = 0.0f;
        if (c + lane < cnt) {
            myIdx = PI[c + lane];
            myP = PV[c + lane];
        }
        int nn = min(32, cnt - c);
#pragma unroll 8
        for (int jj = 0; jj < nn; jj++) {
            int idx = __shfl_sync(0xFFFFFFFFu, myIdx, jj);
            float p = __shfl_sync(0xFFFFFFFFu, myP, jj);
            float2 v = *(const float2*)&Vb[(size_t)idx * HDIM + lane * 2];
            a0 = fmaf(p, v.x, a0);
            a1 = fmaf(p, v.y, a1);
        }
    }

    float2* dst = (float2*)&g_O[(size_t)(b * SEQ + s) * DMODEL + h * HDIM + lane * 2];
    *dst = make_float2(a0, a1);
}

// ---------------- launch ------------------------------------------------------
extern "C" void kernel_launch(void* const* d_in, const int* in_sizes, int n_in,
                              void* d_out, int out_size)
{
    const float* h_ssm = (const float*)d_in[0];
    const float* gate  = (const float*)d_in[1];
    const float* Wq = (const float*)d_in[2];
    const float* bq = (const float*)d_in[3];
    const float* Wk = (const float*)d_in[4];
    const float* bk = (const float*)d_in[5];
    const float* Wv = (const float*)d_in[6];
    const float* bv = (const float*)d_in[7];
    const float* Wo = (const float*)d_in[8];
    const float* bo = (const float*)d_in[9];
    float* out = (float*)d_out;

    cudaFuncSetAttribute(scores_kernel,
                         cudaFuncAttributeMaxDynamicSharedMemorySize, SCORES_SMEM);

    dim3 gProj(DMODEL / 128, NROWS / 128);          // (8, 32)
    qk_proj_kernel<<<dim3(DMODEL / 128, NROWS / 128, 2), 256>>>(h_ssm, Wq, bq, Wk, bk);
    gemm_bf16_kernel<<<gProj, 256>>>(h_ssm, Wv, bv, nullptr, nullptr, 2);

    scores_kernel<<<dim3(SEQ / 128, SEQ / 128, BH), 256, SCORES_SMEM>>>();
    topk_softmax_kernel<<<dim3(BH * SEQ), 256>>>();
    av_sparse_kernel<<<dim3(BH * SEQ / 8), 256>>>();

    gemm_bf16_kernel<<<gProj, 256>>>(nullptr, Wo, bo, out, gate, 3);
}